// round 11
// baseline (speedup 1.0000x reference)
#include <cuda_runtime.h>
#include <cuda_bf16.h>
#include <math.h>
#include <stdint.h>

#define BATCH 8
#define NPTS  500
#define MHYP  144

// table offsets (floats): L0: 8*48*64=24576 ; L1: +8*96*128 -> 122880 ; total +8*192*256
#define TAB_TOTAL 516096

__device__ float g_tabS [TAB_TOTAL];
__device__ float g_tabCh[TAB_TOTAL];
__device__ float g_tabCv[TAB_TOTAL];
__device__ float g_tabCd[TAB_TOTAL];
__device__ float g_tabCa[TAB_TOTAL];
__device__ float g_Tcur [BATCH * 16 * 16];   // only m<16 stored now
__device__ float g_costs[BATCH * 16];

// ---------------- JAX threefry2x32 (bit-exact) ----------------
__device__ __forceinline__ void threefry2x32(uint32_t k0, uint32_t k1,
                                             uint32_t c0, uint32_t c1,
                                             uint32_t& o0, uint32_t& o1)
{
    uint32_t ks0 = k0, ks1 = k1, ks2 = k0 ^ k1 ^ 0x1BD11BDAu;
    uint32_t x0 = c0 + ks0;
    uint32_t x1 = c1 + ks1;
#define TF_ROT(v,d) (((v) << (d)) | ((v) >> (32 - (d))))
#define TF_R(r) { x0 += x1; x1 = TF_ROT(x1, r); x1 ^= x0; }
    TF_R(13) TF_R(15) TF_R(26) TF_R(6)   x0 += ks1; x1 += ks2 + 1u;
    TF_R(17) TF_R(29) TF_R(16) TF_R(24)  x0 += ks2; x1 += ks0 + 2u;
    TF_R(13) TF_R(15) TF_R(26) TF_R(6)   x0 += ks0; x1 += ks1 + 3u;
    TF_R(17) TF_R(29) TF_R(16) TF_R(24)  x0 += ks1; x1 += ks2 + 4u;
    TF_R(13) TF_R(15) TF_R(26) TF_R(6)   x0 += ks2; x1 += ks0 + 5u;
#undef TF_R
#undef TF_ROT
    o0 = x0; o1 = x1;
}

__device__ __forceinline__ uint32_t tf_bits_partitionable(uint32_t k0, uint32_t k1,
                                                          uint32_t i)
{
    uint32_t o0, o1;
    threefry2x32(k0, k1, 0u, i, o0, o1);
    return o0 ^ o1;
}

__device__ __forceinline__ float bits_to_normal(uint32_t bits)
{
    float f  = __uint_as_float((bits >> 9) | 0x3F800000u) - 1.0f;
    float lo = __uint_as_float(0xBF7FFFFFu); // nextafter(-1, 0)
    float u  = fmaxf(lo, f * 2.0f + lo);
    return 1.41421356237309515f * erfinvf(u);
}

// ---------------- SE(3) helpers ----------------
__device__ __forceinline__ void se3_exp(const float xi[6], float T[16])
{
    float wx = xi[3], wy = xi[4], wz = xi[5];
    float nw = sqrtf(wx*wx + wy*wy + wz*wz);
    float theta = fmaxf(nw, 1e-8f);
    float inv = 1.0f / theta;
    float ux = wx * inv, uy = wy * inv, uz = wz * inv;
    float K[9] = {0.f, -uz, uy,  uz, 0.f, -ux,  -uy, ux, 0.f};
    float KK[9];
#pragma unroll
    for (int r = 0; r < 3; r++)
#pragma unroll
        for (int c = 0; c < 3; c++)
            KK[r*3+c] = K[r*3+0]*K[0*3+c] + K[r*3+1]*K[1*3+c] + K[r*3+2]*K[2*3+c];
    float st = sinf(theta);
    float ct = 1.0f - cosf(theta);
    float cth = ct * inv;
    float sth = 1.0f - st * inv;
    float R[9], V[9];
#pragma unroll
    for (int k = 0; k < 9; k++) {
        float eye = (k == 0 || k == 4 || k == 8) ? 1.0f : 0.0f;
        R[k] = eye + st  * K[k] + ct  * KK[k];
        V[k] = eye + cth * K[k] + sth * KK[k];
    }
    float t0 = V[0]*xi[0] + V[1]*xi[1] + V[2]*xi[2];
    float t1 = V[3]*xi[0] + V[4]*xi[1] + V[5]*xi[2];
    float t2 = V[6]*xi[0] + V[7]*xi[1] + V[8]*xi[2];
    T[0]=R[0]; T[1]=R[1]; T[2]=R[2];  T[3]=t0;
    T[4]=R[3]; T[5]=R[4]; T[6]=R[5];  T[7]=t1;
    T[8]=R[6]; T[9]=R[7]; T[10]=R[8]; T[11]=t2;
    T[12]=0.f; T[13]=0.f; T[14]=0.f;  T[15]=1.f;
}

__device__ __forceinline__ void mat4_mul(const float* A, const float* B, float* C)
{
#pragma unroll
    for (int r = 0; r < 4; r++)
#pragma unroll
        for (int c = 0; c < 4; c++)
            C[r*4+c] = A[r*4+0]*B[0*4+c] + A[r*4+1]*B[1*4+c]
                     + A[r*4+2]*B[2*4+c] + A[r*4+3]*B[3*4+c];
}

__device__ __forceinline__ float geod_norm(const float T[16])
{
    float tr = T[0] + T[5] + T[10];
    float ca = (tr - 1.0f) * 0.5f;
    ca = fminf(fmaxf(ca, -1.0f + 1e-7f), 1.0f - 1e-7f);
    float theta = acosf(ca);
    float th = fmaxf(theta, 1e-8f);
    float s  = fmaxf(sinf(th), 1e-8f);
    float k  = th / (2.0f * s);
    float wx = (T[9] - T[6]) * k;
    float wy = (T[2] - T[8]) * k;
    float wz = (T[4] - T[1]) * k;
    if (fabsf(theta) < 1e-6f) { wx = 0.f; wy = 0.f; wz = 0.f; }
    float tx = T[3], ty = T[7], tz = T[11];
    return sqrtf(tx*tx + ty*ty + tz*tz + wx*wx + wy*wy + wz*wz);
}

// hypothesis pose for (b, m): dT(m) @ Tpred[b]
__device__ __forceinline__ void hyp_pose(const float* __restrict__ Tpred,
                                         int b, int m, float T[16])
{
    uint32_t hk0, hk1;
    threefry2x32(0u, 42u, 0u, 0u, hk0, hk1);     // fold_in(key(42), 0)
    float n0 = bits_to_normal(tf_bits_partitionable(hk0, hk1, (uint32_t)(m*3+0)));
    float n1 = bits_to_normal(tf_bits_partitionable(hk0, hk1, (uint32_t)(m*3+1)));
    float n2 = bits_to_normal(tf_bits_partitionable(hk0, hk1, (uint32_t)(m*3+2)));
    const float D2R = 0.017453292519943295f;
    float pitch = (-11.0f + 2.0f * (float)(m / 12)) * D2R;
    float yaw   = (-11.0f + 2.0f * (float)(m % 12)) * D2R;
    float xi[6] = { n0, n1, n2, 0.0f, pitch, yaw };
    float dT[16]; se3_exp(xi, dT);
    mat4_mul(dT, Tpred + b * 16, T);
}

// ---------------- Kernel 1a: Gram tables for L0+L1 (channel-split + smem reduce) ----------------
#define GPITCH 21
__global__ __launch_bounds__(256)
void gram01(const float* __restrict__ q0, const float* __restrict__ q1,
            const float* __restrict__ r0, const float* __restrict__ r1)
{
    __shared__ float sbuf[256 * GPITCH];   // 21.5 KB
    const int blk = blockIdx.x;            // 0..287
    const int tid = threadIdx.x;

    int qbase, nOut, gshift, lgW4, H, W, C, Off;
    const float* __restrict__ qp;
    const float* __restrict__ rp;
    if (blk < 96) { qbase = blk * 64;         nOut = 64;  gshift = 6; lgW4 = 4; H = 48; W = 64;  C = 128; Off = 0;     qp = q0; rp = r0; }
    else          { qbase = (blk - 96) * 128; nOut = 128; gshift = 7; lgW4 = 5; H = 96; W = 128; C = 64;  Off = 24576; qp = q1; rp = r1; }

    const int p    = tid & (nOut - 1);
    const int g    = tid >> gshift;
    const int quad = qbase + p;
    const int W4   = 1 << lgW4;
    const int x4   = quad & (W4 - 1);
    const int y    = (quad >> lgW4) % H;
    const int b    = (quad >> lgW4) / H;
    const int yd   = min(y + 1, H - 1);
    const int x    = x4 << 2;
    const int lane = tid & 31;
    const bool rowend      = (x4 == W4 - 1);
    const bool need_scalar = (!rowend) && (lane == 31);

    const int chs = H * W;
    const int c0c = g * 32;
    const float* qy = qp + ((b * C + c0c) * H + y)  * W + x;
    const float* ry = rp + ((b * C + c0c) * H + y)  * W + x;
    const float* qd = qp + ((b * C + c0c) * H + yd) * W + x;
    const float* rd = rp + ((b * C + c0c) * H + yd) * W + x;

    float vS0=0,vS1=0,vS2=0,vS3=0;
    float vH0=0,vH1=0,vH2=0,vH3=0;
    float vV0=0,vV1=0,vV2=0,vV3=0;
    float vD0=0,vD1=0,vD2=0,vD3=0;
    float vA0=0,vA1=0,vA2=0,vA3=0;

#pragma unroll 4
    for (int c = 0; c < 32; c++) {
        float4 qa = *(const float4*)qy;
        float4 ra = *(const float4*)ry;
        float4 qc = *(const float4*)qd;
        float4 rc = *(const float4*)rd;
        float a0 = qa.x - ra.x, a1 = qa.y - ra.y, a2 = qa.z - ra.z, a3 = qa.w - ra.w;
        float c0 = qc.x - rc.x, c1 = qc.y - rc.y, c2 = qc.z - rc.z, c3 = qc.w - rc.w;
        float an = __shfl_down_sync(0xFFFFFFFFu, a0, 1);
        float cn = __shfl_down_sync(0xFFFFFFFFu, c0, 1);
        if (need_scalar) { an = qy[4] - ry[4]; cn = qd[4] - rd[4]; }
        if (rowend)      { an = a3; cn = c3; }

        vS0 += a0*a0; vS1 += a1*a1; vS2 += a2*a2; vS3 += a3*a3;
        vH0 += a0*a1; vH1 += a1*a2; vH2 += a2*a3; vH3 += a3*an;
        vV0 += a0*c0; vV1 += a1*c1; vV2 += a2*c2; vV3 += a3*c3;
        vD0 += a0*c1; vD1 += a1*c2; vD2 += a2*c3; vD3 += a3*cn;
        vA0 += a1*c0; vA1 += a2*c1; vA2 += a3*c2; vA3 += an*c3;

        qy += chs; ry += chs; qd += chs; rd += chs;
    }

    float* sp = &sbuf[tid * GPITCH];
    sp[0]=vS0; sp[1]=vS1; sp[2]=vS2; sp[3]=vS3;
    sp[4]=vH0; sp[5]=vH1; sp[6]=vH2; sp[7]=vH3;
    sp[8]=vV0; sp[9]=vV1; sp[10]=vV2; sp[11]=vV3;
    sp[12]=vD0; sp[13]=vD1; sp[14]=vD2; sp[15]=vD3;
    sp[16]=vA0; sp[17]=vA1; sp[18]=vA2; sp[19]=vA3;
    __syncthreads();

    if (tid < nOut) {
        float acc[20];
        const float* s0 = &sbuf[tid * GPITCH];
#pragma unroll
        for (int k = 0; k < 20; k++) acc[k] = s0[k];
        for (int gg = 1; gg < (256 / nOut); gg++) {
            const float* sg = &sbuf[(gg * nOut + tid) * GPITCH];
#pragma unroll
            for (int k = 0; k < 20; k++) acc[k] += sg[k];
        }
        int o = Off + (b * H + y) * W + x;
        *(float4*)&g_tabS [o] = make_float4(acc[0],  acc[1],  acc[2],  acc[3]);
        *(float4*)&g_tabCh[o] = make_float4(acc[4],  acc[5],  acc[6],  acc[7]);
        *(float4*)&g_tabCv[o] = make_float4(acc[8],  acc[9],  acc[10], acc[11]);
        *(float4*)&g_tabCd[o] = make_float4(acc[12], acc[13], acc[14], acc[15]);
        *(float4*)&g_tabCa[o] = make_float4(acc[16], acc[17], acc[18], acc[19]);
    }
}

// ---------------- Kernel 1b: Gram tables for L2, row-pair tiling ----------------
// Each thread: 2 output rows (y0, y0+1) from 3 loaded rows, 32 channels, direct write.
// 49152 threads = 192 blocks.
__global__ __launch_bounds__(256)
void gram2(const float* __restrict__ q2, const float* __restrict__ r2)
{
    const int t = blockIdx.x * 256 + threadIdx.x;
    const int W = 256, H = 192, C = 32;
    const int x4 = t & 63;
    const int rest = t >> 6;           // 0 .. 8*96-1
    const int yh = rest % 96;
    const int b  = rest / 96;
    const int y0 = yh * 2;
    const int y2 = min(y0 + 2, H - 1);
    const int x  = x4 << 2;
    const int lane = threadIdx.x & 31;
    const bool rowend      = (x4 == 63);
    const bool need_scalar = (!rowend) && (lane == 31);

    const int chs = H * W;
    const float* qA = q2 + ((size_t)b * C * H + y0)     * W + x;
    const float* rA = r2 + ((size_t)b * C * H + y0)     * W + x;
    const float* qB = q2 + ((size_t)b * C * H + y0 + 1) * W + x;
    const float* rB = r2 + ((size_t)b * C * H + y0 + 1) * W + x;
    const float* qC = q2 + ((size_t)b * C * H + y2)     * W + x;
    const float* rC = r2 + ((size_t)b * C * H + y2)     * W + x;

    float uS0=0,uS1=0,uS2=0,uS3=0, uH0=0,uH1=0,uH2=0,uH3=0;
    float uV0=0,uV1=0,uV2=0,uV3=0, uD0=0,uD1=0,uD2=0,uD3=0;
    float uA0=0,uA1=0,uA2=0,uA3=0;
    float wS0=0,wS1=0,wS2=0,wS3=0, wH0=0,wH1=0,wH2=0,wH3=0;
    float wV0=0,wV1=0,wV2=0,wV3=0, wD0=0,wD1=0,wD2=0,wD3=0;
    float wA0=0,wA1=0,wA2=0,wA3=0;

#pragma unroll 2
    for (int c = 0; c < 32; c++) {
        float4 qa = *(const float4*)qA;  float4 ra = *(const float4*)rA;
        float4 qb = *(const float4*)qB;  float4 rb = *(const float4*)rB;
        float4 qc = *(const float4*)qC;  float4 rc = *(const float4*)rC;
        float a0 = qa.x - ra.x, a1 = qa.y - ra.y, a2 = qa.z - ra.z, a3 = qa.w - ra.w;
        float b0 = qb.x - rb.x, b1 = qb.y - rb.y, b2 = qb.z - rb.z, b3 = qb.w - rb.w;
        float c0 = qc.x - rc.x, c1 = qc.y - rc.y, c2 = qc.z - rc.z, c3 = qc.w - rc.w;
        float an = __shfl_down_sync(0xFFFFFFFFu, a0, 1);
        float bn = __shfl_down_sync(0xFFFFFFFFu, b0, 1);
        float cn = __shfl_down_sync(0xFFFFFFFFu, c0, 1);
        if (need_scalar) { an = qA[4] - rA[4]; bn = qB[4] - rB[4]; cn = qC[4] - rC[4]; }
        if (rowend)      { an = a3; bn = b3; cn = c3; }

        // output row y0: (self=a, down=b)
        uS0 += a0*a0; uS1 += a1*a1; uS2 += a2*a2; uS3 += a3*a3;
        uH0 += a0*a1; uH1 += a1*a2; uH2 += a2*a3; uH3 += a3*an;
        uV0 += a0*b0; uV1 += a1*b1; uV2 += a2*b2; uV3 += a3*b3;
        uD0 += a0*b1; uD1 += a1*b2; uD2 += a2*b3; uD3 += a3*bn;
        uA0 += a1*b0; uA1 += a2*b1; uA2 += a3*b2; uA3 += an*b3;
        // output row y0+1: (self=b, down=c)
        wS0 += b0*b0; wS1 += b1*b1; wS2 += b2*b2; wS3 += b3*b3;
        wH0 += b0*b1; wH1 += b1*b2; wH2 += b2*b3; wH3 += b3*bn;
        wV0 += b0*c0; wV1 += b1*c1; wV2 += b2*c2; wV3 += b3*c3;
        wD0 += b0*c1; wD1 += b1*c2; wD2 += b2*c3; wD3 += b3*cn;
        wA0 += b1*c0; wA1 += b2*c1; wA2 += b3*c2; wA3 += bn*c3;

        qA += chs; rA += chs; qB += chs; rB += chs; qC += chs; rC += chs;
    }

    const int o0 = 122880 + (b * H + y0) * W + x;
    const int o1 = o0 + W;
    *(float4*)&g_tabS [o0] = make_float4(uS0, uS1, uS2, uS3);
    *(float4*)&g_tabCh[o0] = make_float4(uH0, uH1, uH2, uH3);
    *(float4*)&g_tabCv[o0] = make_float4(uV0, uV1, uV2, uV3);
    *(float4*)&g_tabCd[o0] = make_float4(uD0, uD1, uD2, uD3);
    *(float4*)&g_tabCa[o0] = make_float4(uA0, uA1, uA2, uA3);
    *(float4*)&g_tabS [o1] = make_float4(wS0, wS1, wS2, wS3);
    *(float4*)&g_tabCh[o1] = make_float4(wH0, wH1, wH2, wH3);
    *(float4*)&g_tabCv[o1] = make_float4(wV0, wV1, wV2, wV3);
    *(float4*)&g_tabCd[o1] = make_float4(wD0, wD1, wD2, wD3);
    *(float4*)&g_tabCa[o1] = make_float4(wA0, wA1, wA2, wA3);
}

// ---------------- Kernel 2: fused 9 LM iterations (self-contained hyp init) ----------------
__global__ __launch_bounds__(256)
void fused_iter(const float* __restrict__ Tpred,
                const float* __restrict__ geo,
                const float* __restrict__ Kin,
                const float* __restrict__ u0,
                const float* __restrict__ u1,
                const float* __restrict__ u2)
{
    const int b = blockIdx.x >> 4;
    const int m = blockIdx.x & 15;
    const int tid = threadIdx.x;

    __shared__ float sT[16];
    __shared__ float sgeo[NPTS * 3];
    __shared__ float sxi[6];
    __shared__ float sred[8];

    // in-block hypothesis init (redundant across threads; tid<16 commit)
    {
        float Th[16]; hyp_pose(Tpred, b, m, Th);
        if (tid < 16) sT[tid] = Th[tid];
    }
    for (int i = tid; i < NPTS * 3; i += 256) sgeo[i] = geo[b * NPTS * 3 + i];
    __syncthreads();

    const int   itH[9]    = {48,48, 96,96,96, 192,192,192,192};
    const int   itW[9]    = {64,64, 128,128,128, 256,256,256,256};
    const int   itOff[9]  = {0,0, 24576,24576,24576, 122880,122880,122880,122880};
    const float itScl[9]  = {0.25f,0.25f, 0.5f,0.5f,0.5f, 1.0f,1.0f,1.0f,1.0f};
    const float itDmp[9]  = {0.001f,0.001f, 0.0005f,0.0005f,0.0005f,
                             0.00025f,0.00025f,0.00025f,0.00025f};
    const uint32_t itDat[9] = {100u,101u, 110u,111u,112u, 120u,121u,122u,123u};

    const float fxK = Kin[b*9+0], cxK = Kin[b*9+2];
    const float fyK = Kin[b*9+4], cyK = Kin[b*9+5];

    for (int it = 0; it < 9; it++) {
        if (tid < 6) {
            uint32_t hk0, hk1;
            threefry2x32(0u, 42u, 0u, itDat[it], hk0, hk1);
            uint32_t i = (uint32_t)((b * MHYP + m) * 6 + tid);
            sxi[tid] = bits_to_normal(tf_bits_partitionable(hk0, hk1, i));
        }

        const int H = itH[it], W = itW[it];
        const float scale = itScl[it];
        const float fx = fxK * scale, cx = cxK * scale;
        const float fy = fyK * scale, cy = cyK * scale;
        const float* U = ((it < 2) ? u0 : ((it < 5) ? u1 : u2)) + b * H * W;
        const int tb = itOff[it] + b * H * W;
        const float Wm1 = (float)(W - 1), Hm1 = (float)(H - 1);
        const float Wf = (float)W, Hf = (float)H;

        float local = 0.0f;
        for (int n = tid; n < NPTS; n += 256) {
            float X = sgeo[n*3 + 0];
            float Y = sgeo[n*3 + 1];
            float Z = sgeo[n*3 + 2];
            float pc0 = sT[0]*X + sT[1]*Y + sT[2]*Z  + sT[3];
            float pc1 = sT[4]*X + sT[5]*Y + sT[6]*Z  + sT[7];
            float pc2 = sT[8]*X + sT[9]*Y + sT[10]*Z + sT[11];
            float z = fmaxf(pc2, 1e-6f);
            float uu = fx * (pc0 / z) + cx;
            float vv = fy * (pc1 / z) + cy;
            float gx = 2.0f * uu / Wm1 - 1.0f;
            float gy = 2.0f * vv / Hm1 - 1.0f;
            float xx = fminf(fmaxf(((gx + 1.0f) * Wf - 1.0f) * 0.5f, 0.0f), Wm1);
            float yy = fminf(fmaxf(((gy + 1.0f) * Hf - 1.0f) * 0.5f, 0.0f), Hm1);
            float x0f = floorf(xx), y0f = floorf(yy);
            float wx = xx - x0f, wy = yy - y0f;
            int x0 = (int)x0f, y0 = (int)y0f;
            int x1 = min(x0 + 1, W - 1), y1 = min(y0 + 1, H - 1);
            float ox = 1.0f - wx, oy = 1.0f - wy;
            float w00 = ox*oy, wX0 = wx*oy, w0Y = ox*wy, wXY = wx*wy;
            int i00 = tb + y0*W + x0;
            int i10 = tb + y0*W + x1;
            int i01 = tb + y1*W + x0;
            int i11 = tb + y1*W + x1;
            float S00 = __ldg(&g_tabS[i00]);
            float S10 = __ldg(&g_tabS[i10]);
            float S01 = __ldg(&g_tabS[i01]);
            float S11 = __ldg(&g_tabS[i11]);
            float ChA = __ldg(&g_tabCh[i00]);
            float ChB = __ldg(&g_tabCh[i01]);
            float CvA = __ldg(&g_tabCv[i00]);
            float CvB = __ldg(&g_tabCv[i10]);
            float CdA = __ldg(&g_tabCd[i00]);
            float CaA = __ldg(&g_tabCa[i00]);
            float quad = w00*w00*S00 + wX0*wX0*S10 + w0Y*w0Y*S01 + wXY*wXY*S11
                       + 2.0f*(w00*wX0*ChA + w0Y*wXY*ChB + w00*w0Y*CvA
                             + wX0*wXY*CvB + w00*wXY*CdA + wX0*w0Y*CaA);
            float us = __ldg(&U[y0*W + x0]) * w00 + __ldg(&U[y0*W + x1]) * wX0
                     + __ldg(&U[y1*W + x0]) * w0Y + __ldg(&U[y1*W + x1]) * wXY;
            local += quad * us;
        }
#pragma unroll
        for (int off = 16; off > 0; off >>= 1)
            local += __shfl_xor_sync(0xFFFFFFFFu, local, off);
        if ((tid & 31) == 0) sred[tid >> 5] = local;
        __syncthreads();

        float s = 0.0f;
#pragma unroll
        for (int w = 0; w < 8; w++) s += sred[w];
        float res = s / (float)NPTS;
        if (tid == 0) g_costs[b * 16 + m] = res;
        float a1 = -itDmp[it] * res;
        float xi[6];
#pragma unroll
        for (int k = 0; k < 6; k++) xi[k] = a1 * sxi[k] * 0.01f;
        float dT[16]; se3_exp(xi, dT);
        float Told[16];
#pragma unroll
        for (int k = 0; k < 16; k++) Told[k] = sT[k];
        float Tn[16]; mat4_mul(dT, Told, Tn);
        __syncthreads();
        if (tid < 16) sT[tid] = Tn[tid];
        __syncthreads();
    }

    if (tid < 16) g_Tcur[(b * 16 + m) * 16 + tid] = sT[tid];
}

// ---------------- Kernel 3: finalize (inline hyp for m>=16, parallel argmin) ----------------
__global__ void final_kernel(const float* __restrict__ Tpred, float* __restrict__ out)
{
    const int b = blockIdx.x;
    const int t = threadIdx.x; // 160 threads (5 warps)
    __shared__ float sInv[16];
    __shared__ unsigned long long swarp[5];
    __shared__ int sBest;
    if (t == 0) {
        const float* Tp = Tpred + b * 16;
        sInv[0]=Tp[0]; sInv[1]=Tp[4]; sInv[2] =Tp[8];
        sInv[4]=Tp[1]; sInv[5]=Tp[5]; sInv[6] =Tp[9];
        sInv[8]=Tp[2]; sInv[9]=Tp[6]; sInv[10]=Tp[10];
        sInv[3]  = -(Tp[0]*Tp[3] + Tp[4]*Tp[7] + Tp[8]*Tp[11]);
        sInv[7]  = -(Tp[1]*Tp[3] + Tp[5]*Tp[7] + Tp[9]*Tp[11]);
        sInv[11] = -(Tp[2]*Tp[3] + Tp[6]*Tp[7] + Tp[10]*Tp[11]);
        sInv[12]=0.f; sInv[13]=0.f; sInv[14]=0.f; sInv[15]=1.f;
    }
    __syncthreads();

    float T[16];
    unsigned long long key = 0xFFFFFFFFFFFFFFFFull;
    if (t < MHYP) {
        float c = 0.0f;
        if (t < 16) {
#pragma unroll
            for (int k = 0; k < 16; k++) T[k] = g_Tcur[(b * 16 + t) * 16 + k];
            c = g_costs[b * 16 + t];
        } else {
            hyp_pose(Tpred, b, t, T);     // never LM-updated (step=0 -> identity)
        }
        float Trel[16]; mat4_mul(T, sInv, Trel);
        float tot = c + geod_norm(Trel);  // >= 0 -> float bits order-monotonic
        out[BATCH * 16 + b * MHYP + t] = c;
        key = ((unsigned long long)__float_as_uint(tot) << 32) | (unsigned)t;
    }
#pragma unroll
    for (int off = 16; off > 0; off >>= 1) {
        unsigned long long o = __shfl_xor_sync(0xFFFFFFFFu, key, off);
        key = (o < key) ? o : key;
    }
    if ((t & 31) == 0) swarp[t >> 5] = key;
    __syncthreads();
    if (t == 0) {
        unsigned long long kk = swarp[0];
#pragma unroll
        for (int w = 1; w < 5; w++) kk = (swarp[w] < kk) ? swarp[w] : kk;
        sBest = (int)(kk & 0xFFFFFFFFull);
    }
    __syncthreads();
    if (t == sBest) {
#pragma unroll
        for (int k = 0; k < 16; k++) out[b * 16 + k] = T[k];
    }
}

// ---------------- launch ----------------
extern "C" void kernel_launch(void* const* d_in, const int* in_sizes, int n_in,
                              void* d_out, int out_size)
{
    const float* Tpred = (const float*)d_in[0];
    const float* geo   = (const float*)d_in[1];
    const float* Kin   = (const float*)d_in[2];
    const float* q0 = (const float*)d_in[3];
    const float* q1 = (const float*)d_in[4];
    const float* q2 = (const float*)d_in[5];
    const float* r0 = (const float*)d_in[6];
    const float* r1 = (const float*)d_in[7];
    const float* r2 = (const float*)d_in[8];
    const float* u0 = (const float*)d_in[9];
    const float* u1 = (const float*)d_in[10];
    const float* u2 = (const float*)d_in[11];
    float* out = (float*)d_out;

    gram01<<<288, 256>>>(q0, q1, r0, r1);
    gram2<<<192, 256>>>(q2, r2);
    fused_iter<<<BATCH * 16, 256>>>(Tpred, geo, Kin, u0, u1, u2);
    final_kernel<<<BATCH, 160>>>(Tpred, out);
}